// round 15
// baseline (speedup 1.0000x reference)
#include <cuda_runtime.h>
#include <cuda_bf16.h>

// Problem constants
#define BATCH 16
#define NPTS 2048
#define NUM_CLASSES 40
#define NB 64                        // z-buckets
#define ZMIN (-3.5f)
#define ZRANGE 7.0f
#define HBUK (ZRANGE / NB)
#define INVH (NB / ZRANGE)
#define MAXPAIRS (NPTS / 2 + NB)     // 1088 pair-padded
#define NCLOUD 32                    // 16 reg + 16 p1

// chamfer kernel geometry
#define TB 128                       // threads per block
#define QPB 128                      // queries per block
#define NCHUNK (NPTS / QPB)          // 16
#define NBLOCKS (2 * BATCH * NCHUNK) // 512

// Device scratch (no allocation allowed) — bucketed tiles live in L2
__device__ float4 g_tileA[NCLOUD][MAXPAIRS];   // (x0,x1,y0,y1) per pair
__device__ float4 g_tileB[NCLOUD][MAXPAIRS];   // (z0,z1,w0,w1) per pair
__device__ int    g_pstart[NCLOUD][NB + 1];
__device__ float  g_partials[NBLOCKS];
__device__ int    g_count = 0;                 // self-resetting counter

// Packed f32x2 helpers (sm_103a FFMA2 — only reachable via PTX)
#define FMA2(acc, a, b) \
    asm("fma.rn.f32x2 %0, %1, %2, %0;" : "+l"(acc) : "l"(a), "l"(b))
#define FMA2_3(dst, a, b, c) \
    asm("fma.rn.f32x2 %0, %1, %2, %3;" : "=l"(dst) : "l"(a), "l"(b), "l"(c))
#define PACK_REP(dst, s) \
    asm("mov.b64 %0, {%1, %1};" : "=l"(dst) : "f"(s))
#define UNPACK2(lo, hi, src) \
    asm("mov.b64 {%0, %1}, %2;" : "=f"(lo), "=f"(hi) : "l"(src))

__device__ __forceinline__ int bucket_of(float z) {
    int b = (int)((z - ZMIN) * INVH);
    return b < 0 ? 0 : (b > NB - 1 ? NB - 1 : b);
}

// ---------------------------------------------------------------------------
// Kernel A: bucket one cloud per block into pair-interleaved global tiles.
// Scatter order within a bucket is atomic-nondeterministic, but min over a
// bucket is order-invariant (same multiset), so results stay deterministic.
// ---------------------------------------------------------------------------
__global__ __launch_bounds__(256)
void bucket_kernel(const float* __restrict__ reg,
                   const float* __restrict__ p1) {
    __shared__ float4 sTA[MAXPAIRS];
    __shared__ float4 sTB[MAXPAIRS];
    __shared__ int cnt[NB], fill[NB], pstart[NB + 1];

    const int cloud = blockIdx.x;                      // 0..31
    const float* yb = (cloud < 16) ? (reg + (size_t)cloud * NPTS * 3)
                                   : (p1 + (size_t)(cloud - 16) * NPTS * 3);
    const int tid = threadIdx.x, lane = tid & 31;

    if (tid < NB) { cnt[tid] = 0; fill[tid] = 0; }
    __syncthreads();

    // Load 8 points/thread, histogram
    float tx[8], ty[8], tz[8];
    int   tk[8];
    #pragma unroll
    for (int k = 0; k < 8; k++) {
        const int i = tid + 256 * k;
        tx[k] = yb[i * 3 + 0];
        ty[k] = yb[i * 3 + 1];
        tz[k] = yb[i * 3 + 2];
        tk[k] = bucket_of(tz[k]);
        atomicAdd(&cnt[tk[k]], 1);
    }
    __syncthreads();

    // Pair-count prefix scan (warp 0, 2 buckets/lane)
    if (tid < 32) {
        const int pc0 = (cnt[2 * tid] + 1) >> 1, pc1 = (cnt[2 * tid + 1] + 1) >> 1;
        int s = pc0 + pc1, inc = s;
        #pragma unroll
        for (int off = 1; off < 32; off <<= 1) {
            const int t = __shfl_up_sync(0xFFFFFFFFu, inc, off);
            if (lane >= off) inc += t;
        }
        pstart[2 * tid]     = inc - s;
        pstart[2 * tid + 1] = inc - pc1;
        if (tid == 31) pstart[NB] = inc;
    }
    __syncthreads();

    // Sentinel init full tile, then scatter
    for (int j = tid; j < MAXPAIRS; j += 256) {
        sTA[j] = make_float4(0.f, 0.f, 0.f, 0.f);
        sTB[j] = make_float4(0.f, 0.f, 1e30f, 1e30f);
    }
    __syncthreads();
    #pragma unroll
    for (int k = 0; k < 8; k++) {
        const float w = tx[k] * tx[k] + ty[k] * ty[k] + tz[k] * tz[k];
        const int bb  = tk[k];
        const int pos = atomicAdd(&fill[bb], 1);
        const int pr  = pstart[bb] + (pos >> 1);
        const int hf  = pos & 1;
        float* A  = (float*)&sTA[pr];
        float* Bp = (float*)&sTB[pr];
        A[hf] = tx[k]; A[2 + hf] = ty[k]; Bp[hf] = tz[k]; Bp[2 + hf] = w;
    }
    __syncthreads();

    // Coalesced copy to global
    for (int j = tid; j < MAXPAIRS; j += 256) {
        g_tileA[cloud][j] = sTA[j];
        g_tileB[cloud][j] = sTB[j];
    }
    if (tid <= NB) g_pstart[cloud][tid] = pstart[tid];
}

// ---------------------------------------------------------------------------
// Kernel B: exact z-pruned scan. One block = (dir, batch, 128-query chunk).
// Tile comes pre-bucketed from L2 (coalesced); queries sorted in-block
// deterministically (match_any + shuffle scan) so warps hold z-adjacent
// queries and the bucket window walk is warp-uniform.
// ---------------------------------------------------------------------------
__global__ __launch_bounds__(TB)
void chamfer_kernel(const float* __restrict__ reg,
                    const float* __restrict__ p1,
                    const float* __restrict__ pred,
                    const int*   __restrict__ target32,
                    float* __restrict__ out) {
    __shared__ float4 sTA[MAXPAIRS];
    __shared__ float4 sTB[MAXPAIRS];
    __shared__ float4 sQ[QPB];
    __shared__ int    pstart[NB + 1];
    __shared__ int    qc[4][NB];
    __shared__ int    qtot[NB];
    __shared__ int    qstart[NB];
    __shared__ float  sred[TB];
    __shared__ int    s_last;

    const int blk   = blockIdx.x;
    const int dir   = blk >> 8;          // 512 blocks: bit 8 = direction
    const int rem   = blk & 255;
    const int b     = rem >> 4;
    const int chunk = rem & 15;
    const int tid   = threadIdx.x;
    const int wid   = tid >> 5;          // 0..3
    const int lane  = tid & 31;

    // dir 0: queries = reg[b], targets = p1[b] (cloud 16+b)
    // dir 1: queries = p1[b],  targets = reg[b] (cloud b)
    const int cloud = dir ? b : (16 + b);
    const float* xb = (dir ? p1 : reg) + (size_t)b * NPTS * 3;

    // Tile + pstart load (coalesced, L2-hot)
    for (int j = tid; j < MAXPAIRS; j += TB) {
        sTA[j] = g_tileA[cloud][j];
        sTB[j] = g_tileB[cloud][j];
    }
    if (tid <= NB) pstart[tid] = g_pstart[cloud][tid];
    for (int k = tid; k < 4 * NB; k += TB) ((int*)qc)[k] = 0;
    __syncthreads();

    // Query load + deterministic warp rank
    const int qi = chunk * QPB + tid;
    const float qx = xb[qi * 3 + 0], qy = xb[qi * 3 + 1], qzv = xb[qi * 3 + 2];
    const float qn = qx * qx + qy * qy + qzv * qzv;
    const int qbk = bucket_of(qzv);
    const unsigned msk  = __match_any_sync(0xFFFFFFFFu, qbk);
    const int      rank = __popc(msk & ((1u << lane) - 1u));
    if (rank == 0) qc[wid][qbk] = __popc(msk);
    __syncthreads();

    if (tid < NB)
        qtot[tid] = qc[0][tid] + qc[1][tid] + qc[2][tid] + qc[3][tid];
    __syncthreads();

    if (tid < 32) {   // query-bucket scan, 2 buckets/lane
        const int q0 = qtot[2 * tid], q1 = qtot[2 * tid + 1];
        int s = q0 + q1, inc = s;
        #pragma unroll
        for (int off = 1; off < 32; off <<= 1) {
            const int t = __shfl_up_sync(0xFFFFFFFFu, inc, off);
            if (lane >= off) inc += t;
        }
        qstart[2 * tid]     = inc - s;
        qstart[2 * tid + 1] = inc - q1;
    }
    __syncthreads();

    {
        int woff = 0;
        for (int w = 0; w < wid; w++) woff += qc[w][qbk];
        sQ[qstart[qbk] + woff + rank] = make_float4(qx, qy, qzv, qn);
    }
    __syncthreads();

    // Pruned scan: lane owns sorted query sQ[tid]
    const float4 q = sQ[tid];
    unsigned long long X, Y, Z;
    PACK_REP(X, -2.0f * q.x);
    PACK_REP(Y, -2.0f * q.y);
    PACK_REP(Z, -2.0f * q.z);
    const float qz = q.z, n = q.w;

    const ulonglong2* __restrict__ pTA = reinterpret_cast<const ulonglong2*>(sTA);
    const ulonglong2* __restrict__ pTB = reinterpret_cast<const ulonglong2*>(sTB);

    float ma = 3.0e38f, mb = 3.0e38f;

    #define PROCESS_BUCKET(B) do {                                          \
        int _j = pstart[(B)];                                               \
        const int _e = pstart[(B) + 1];                                     \
        for (; _j + 2 <= _e; _j += 2) {                                     \
            const ulonglong2 a0 = pTA[_j],     b0 = pTB[_j];                \
            const ulonglong2 a1 = pTA[_j + 1], b1 = pTB[_j + 1];            \
            unsigned long long t0, t1;                                      \
            FMA2_3(t0, Z, b0.x, b0.y);  FMA2_3(t1, Z, b1.x, b1.y);          \
            FMA2(t0, Y, a0.y);          FMA2(t1, Y, a1.y);                  \
            FMA2(t0, X, a0.x);          FMA2(t1, X, a1.x);                  \
            float l0, h0, l1, h1;                                           \
            UNPACK2(l0, h0, t0); UNPACK2(l1, h1, t1);                       \
            ma = fminf(ma, fminf(l0, l1));                                  \
            mb = fminf(mb, fminf(h0, h1));                                  \
        }                                                                   \
        if (_j < _e) {                                                      \
            const ulonglong2 a0 = pTA[_j], b0 = pTB[_j];                    \
            unsigned long long t0;                                          \
            FMA2_3(t0, Z, b0.x, b0.y);                                      \
            FMA2(t0, Y, a0.y);                                              \
            FMA2(t0, X, a0.x);                                              \
            float l0, h0; UNPACK2(l0, h0, t0);                              \
            ma = fminf(ma, l0); mb = fminf(mb, h0);                         \
        } } while (0)

    int lo = bucket_of(qz), hi = lo;
    #pragma unroll
    for (int off = 16; off > 0; off >>= 1) {
        lo = min(lo, __shfl_xor_sync(0xFFFFFFFFu, lo, off));
        hi = max(hi, __shfl_xor_sync(0xFFFFFFFFu, hi, off));
    }
    for (int B = lo; B <= hi; B++) PROCESS_BUCKET(B);

    for (int iter = 0; iter < NB; iter++) {
        const float thr = n + fminf(ma, mb);   // current min distance^2
        bool vLo = (lo > 0);
        if (vLo) { const float dz = qz - (ZMIN + lo * HBUK); vLo = dz * dz < thr; }
        bool vHi = (hi < NB - 1);
        if (vHi) { const float dz = (ZMIN + (hi + 1) * HBUK) - qz; vHi = dz * dz < thr; }
        const bool aLo = __any_sync(0xFFFFFFFFu, vLo);
        const bool aHi = __any_sync(0xFFFFFFFFu, vHi);
        if (!aLo && !aHi) break;
        if (aLo) { lo--; PROCESS_BUCKET(lo); }
        if (aHi) { hi++; PROCESS_BUCKET(hi); }
    }
    #undef PROCESS_BUCKET

    // Block reduction of n + min
    sred[tid] = n + fminf(ma, mb);
    __syncthreads();
    if (tid < 64) sred[tid] += sred[tid + 64];
    __syncthreads();
    if (tid < 32) {
        float v = sred[tid] + sred[tid + 32];
        #pragma unroll
        for (int off = 16; off > 0; off >>= 1)
            v += __shfl_down_sync(0xFFFFFFFFu, v, off);
        if (tid == 0) g_partials[blk] = v;
    }

    // Fused finalize: last block sums 512 partials + NLL
    if (tid == 0) {
        __threadfence();
        const int r = atomicAdd(&g_count, 1);
        s_last = (r == NBLOCKS - 1);
    }
    __syncthreads();
    if (!s_last) return;
    __threadfence();

    {
        volatile float* vp = g_partials;
        sred[tid] = (vp[tid] + vp[tid + TB]) + (vp[tid + 2 * TB] + vp[tid + 3 * TB]);
    }
    __syncthreads();
    if (tid < 64) sred[tid] += sred[tid + 64];
    __syncthreads();
    if (tid < 32) {
        float w = sred[tid] + sred[tid + 32];
        #pragma unroll
        for (int off = 16; off > 0; off >>= 1)
            w += __shfl_down_sync(0xFFFFFFFFu, w, off);
        if (tid == 0) {
            const float reg_loss = w / (float)(BATCH * NPTS);

            // dtype sniff: JAX x64-disabled emits int32 despite declared int64.
            bool is64 = true;
            #pragma unroll
            for (int i = 0; i < 8; i++)
                if (target32[2 * i + 1] != 0) is64 = false;

            float nll = 0.0f;
            #pragma unroll
            for (int i = 0; i < BATCH; i++) {
                int t = is64 ? target32[2 * i] : target32[i];
                t = (t < 0) ? 0 : (t >= NUM_CLASSES ? NUM_CLASSES - 1 : t);
                nll -= pred[i * NUM_CLASSES + t];
            }
            nll /= (float)BATCH;
            out[0] = nll + reg_loss;
            g_count = 0;   // self-reset for next graph replay
        }
    }
}

extern "C" void kernel_launch(void* const* d_in, const int* in_sizes, int n_in,
                              void* d_out, int out_size) {
    const float* reg    = (const float*)d_in[0];   // [16, 2048, 3]
    const float* p1     = (const float*)d_in[1];   // [16, 2048, 3]
    const float* pred   = (const float*)d_in[2];   // [16, 40] log-probs
    const int*   target = (const int*)d_in[3];     // [16] int32 (or int64, sniffed)
    float* out = (float*)d_out;

    bucket_kernel<<<NCLOUD, 256>>>(reg, p1);
    chamfer_kernel<<<NBLOCKS, TB>>>(reg, p1, pred, target, out);
}

// round 16
// speedup vs baseline: 1.3038x; 1.3038x over previous
#include <cuda_runtime.h>
#include <cuda_bf16.h>

// Problem constants
#define BATCH 16
#define NPTS 2048
#define NPAIRS 1024
#define NUM_CLASSES 40
#define THREADS 256
#define NQ (2 * BATCH * NPTS)        // 65536 total queries
#define QPB 128                      // queries per block (32 lanes x 4 slots)
#define NCHUNK (NPTS / QPB)          // 16
#define NHALF 2                      // target halves per cloud
#define HPAIRS (NPAIRS / NHALF)      // 512 pairs per half-tile
#define NBLOCKS (2 * BATCH * NCHUNK * NHALF)   // 1024
#define NGROUPS 8                    // 8 warps; each scans 64 pairs
#define PAIRS_PER_GROUP (HPAIRS / NGROUPS)     // 64
#define RBLOCKS 64                   // reduce-kernel blocks

// Device scratch (no allocation allowed)
__device__ unsigned g_qmin[NQ];      // per-query min d^2 (uint-ordered floats)
__device__ float    g_partials[RBLOCKS];
__device__ int      g_count = 0;     // self-resetting counter (reduce kernel)

// Packed f32x2 helpers (sm_103a FFMA2 — only reachable via PTX)
#define FMA2(acc, a, b) \
    asm("fma.rn.f32x2 %0, %1, %2, %0;" : "+l"(acc) : "l"(a), "l"(b))
#define FMA2_3(dst, a, b, c) \
    asm("fma.rn.f32x2 %0, %1, %2, %3;" : "=l"(dst) : "l"(a), "l"(b), "l"(c))
#define PACK_REP(dst, s) \
    asm("mov.b64 %0, {%1, %1};" : "=l"(dst) : "f"(s))
#define UNPACK2(lo, hi, src) \
    asm("mov.b64 {%0, %1}, %2;" : "=f"(lo), "=f"(hi) : "l"(src))

// ---------------------------------------------------------------------------
// k0: reset per-query mins to +inf (every replay; graph-deterministic)
// ---------------------------------------------------------------------------
__global__ void init_kernel() {
    const unsigned INF = 0x7F800000u;
    ((uint4*)g_qmin)[blockIdx.x * 256 + threadIdx.x] = make_uint4(INF, INF, INF, INF);
}

// ---------------------------------------------------------------------------
// k1: brute-force distances, split by target HALF across blocks.
// Block = (dir, batch, 128-query chunk, half). 256 thr = 32 lanes x 8 groups,
// 4 query slots per lane; each thread scans 64 pairs of the 512-pair half.
// Per-query min over the half is combined in-block, then atomicMin'ed into
// g_qmin (uint order == float order for the clamped non-negative d^2; min is
// order-invariant => deterministic). Grid 1024 streams ~4 blocks/SM so the
// SMs stay full (R11's single-wave grid stalled issue at 45%).
// SMEM half-tile, pair-interleaved SoA:
//   sA[p] = (x_{2p}, x_{2p+1}, y_{2p}, y_{2p+1})
//   sB[p] = (z_{2p}, z_{2p+1}, w_{2p}, w_{2p+1})   w = |y|^2
// d(x,y) = |x|^2 + (w - 2 x.y); -2 folded into packed query regs.
// ---------------------------------------------------------------------------
__global__ __launch_bounds__(THREADS, 4)
void chamfer_kernel(const float* __restrict__ reg,
                    const float* __restrict__ p1) {
    __shared__ float4 sA[HPAIRS];          // 8 KB
    __shared__ float4 sB[HPAIRS];          // 8 KB
    __shared__ float  smin[4][THREADS];    // 4 KB

    const int blk   = blockIdx.x;
    const int dir   = blk >> 9;
    const int rem   = blk & 511;
    const int b     = rem >> 5;
    const int rem2  = rem & 31;
    const int chunk = rem2 >> 1;
    const int half  = rem2 & 1;
    const int tid   = threadIdx.x;
    const int lane  = tid & 31;
    const int grp   = tid >> 5;

    const float* __restrict__ xsrc = dir ? p1 : reg;
    const float* __restrict__ ysrc = dir ? reg : p1;
    const float* xb = xsrc + (size_t)b * NPTS * 3;
    const float* yb = ysrc + (size_t)b * NPTS * 3;

    // Fill this half's pair-interleaved tile (2 pairs per thread)
    #pragma unroll
    for (int k = 0; k < HPAIRS / THREADS; k++) {
        const int pl = tid + THREADS * k;
        const int p  = half * HPAIRS + pl;
        const float a0 = yb[6 * p + 0], a1 = yb[6 * p + 1], a2 = yb[6 * p + 2];
        const float b0 = yb[6 * p + 3], b1 = yb[6 * p + 4], b2 = yb[6 * p + 5];
        sA[pl] = make_float4(a0, b0, a1, b1);
        sB[pl] = make_float4(a2, b2,
                             a0 * a0 + a1 * a1 + a2 * a2,
                             b0 * b0 + b1 * b1 + b2 * b2);
    }
    __syncthreads();

    // 4 query points per thread; only packed -2*coord regs stay live
    const int qbase = chunk * QPB + lane;
    unsigned long long X[4], Y[4], Z[4];
    #pragma unroll
    for (int s = 0; s < 4; s++) {
        const int q = qbase + 32 * s;
        PACK_REP(X[s], -2.0f * xb[q * 3 + 0]);
        PACK_REP(Y[s], -2.0f * xb[q * 3 + 1]);
        PACK_REP(Z[s], -2.0f * xb[q * 3 + 2]);
    }

    const ulonglong2* __restrict__ pA = reinterpret_cast<const ulonglong2*>(sA);
    const ulonglong2* __restrict__ pB = reinterpret_cast<const ulonglong2*>(sB);

    float m[4] = {3.0e38f, 3.0e38f, 3.0e38f, 3.0e38f};

    const int pbeg = grp * PAIRS_PER_GROUP;
    #pragma unroll 4
    for (int p = pbeg; p < pbeg + PAIRS_PER_GROUP; p++) {
        const ulonglong2 qa = pA[p];   // .x = xpair, .y = ypair
        const ulonglong2 qb = pB[p];   // .x = zpair, .y = wpair
        #pragma unroll
        for (int s = 0; s < 4; s++) {
            unsigned long long t;
            FMA2_3(t, Z[s], qb.x, qb.y);   // w - 2z*tz
            FMA2(t, Y[s], qa.y);
            FMA2(t, X[s], qa.x);
            float lo, hi; UNPACK2(lo, hi, t);
            m[s] = fminf(m[s], fminf(lo, hi));
        }
    }

    #pragma unroll
    for (int s = 0; s < 4; s++)
        smin[s][tid] = m[s];
    __syncthreads();

    // Warp 0 combines the 8 groups and pushes per-query d^2 via atomicMin
    if (tid < 32) {
        #pragma unroll
        for (int s = 0; s < 4; s++) {
            float mm = smin[s][lane];
            #pragma unroll
            for (int g = 1; g < NGROUPS; g++)
                mm = fminf(mm, smin[s][32 * g + lane]);
            // recover |q|^2 from packed -2x regs
            float xl, xh, yl, yh, zl, zh;
            UNPACK2(xl, xh, X[s]);
            UNPACK2(yl, yh, Y[s]);
            UNPACK2(zl, zh, Z[s]);
            (void)xh; (void)yh; (void)zh;
            const float n = 0.25f * (xl * xl + yl * yl + zl * zl);
            const float v = fmaxf(n + mm, 0.0f);     // d^2 >= 0 (uint-ordered)
            const int qid = (dir * BATCH + b) * NPTS + chunk * QPB + lane + 32 * s;
            atomicMin(&g_qmin[qid], __float_as_uint(v));
        }
    }
}

// ---------------------------------------------------------------------------
// k2: sum the 65536 per-query mins, add NLL, write scalar.
// ---------------------------------------------------------------------------
__global__ __launch_bounds__(THREADS)
void reduce_kernel(const float* __restrict__ pred,
                   const int*   __restrict__ target32,
                   float* __restrict__ out) {
    __shared__ float sred[THREADS];
    __shared__ int   s_last;
    const int tid = threadIdx.x;
    const int blk = blockIdx.x;

    const uint4 v = ((const uint4*)g_qmin)[blk * THREADS + tid];
    float s = (__uint_as_float(v.x) + __uint_as_float(v.y))
            + (__uint_as_float(v.z) + __uint_as_float(v.w));

    sred[tid] = s;
    __syncthreads();
    #pragma unroll
    for (int off = THREADS / 2; off >= 32; off >>= 1) {
        if (tid < off) sred[tid] += sred[tid + off];
        __syncthreads();
    }
    if (tid < 32) {
        float w = sred[tid];
        #pragma unroll
        for (int off = 16; off > 0; off >>= 1)
            w += __shfl_down_sync(0xFFFFFFFFu, w, off);
        if (tid == 0) g_partials[blk] = w;
    }

    if (tid == 0) {
        __threadfence();
        const int r = atomicAdd(&g_count, 1);
        s_last = (r == RBLOCKS - 1);
    }
    __syncthreads();
    if (!s_last) return;
    __threadfence();

    float w = 0.0f;
    if (tid < RBLOCKS) {
        volatile float* vp = g_partials;
        w = vp[tid];
    }
    if (tid < 32) {
        // fold the 64 partials held by lanes 0..63 via shared
        sred[tid] = w;
    }
    if (tid >= 32 && tid < 64) sred[tid] = w;
    __syncthreads();
    if (tid < 32) {
        float v2 = sred[tid] + sred[tid + 32];
        #pragma unroll
        for (int off = 16; off > 0; off >>= 1)
            v2 += __shfl_down_sync(0xFFFFFFFFu, v2, off);
        if (tid == 0) {
            const float reg_loss = v2 / (float)(BATCH * NPTS);

            // dtype sniff: JAX x64-disabled emits int32 despite declared int64.
            bool is64 = true;
            #pragma unroll
            for (int i = 0; i < 8; i++)
                if (target32[2 * i + 1] != 0) is64 = false;

            float nll = 0.0f;
            #pragma unroll
            for (int i = 0; i < BATCH; i++) {
                int t = is64 ? target32[2 * i] : target32[i];
                t = (t < 0) ? 0 : (t >= NUM_CLASSES ? NUM_CLASSES - 1 : t);
                nll -= pred[i * NUM_CLASSES + t];
            }
            nll /= (float)BATCH;
            out[0] = nll + reg_loss;
            g_count = 0;   // self-reset for next graph replay
        }
    }
}

extern "C" void kernel_launch(void* const* d_in, const int* in_sizes, int n_in,
                              void* d_out, int out_size) {
    const float* reg    = (const float*)d_in[0];   // [16, 2048, 3]
    const float* p1     = (const float*)d_in[1];   // [16, 2048, 3]
    const float* pred   = (const float*)d_in[2];   // [16, 40] log-probs
    const int*   target = (const int*)d_in[3];     // [16] int32 (or int64, sniffed)
    float* out = (float*)d_out;

    init_kernel<<<NQ / 1024, 256>>>();
    chamfer_kernel<<<NBLOCKS, THREADS>>>(reg, p1);
    reduce_kernel<<<RBLOCKS, THREADS>>>(pred, target, out);
}